// round 1
// baseline (speedup 1.0000x reference)
#include <cuda_runtime.h>
#include <cuda_bf16.h>
#include <stdint.h>

#define NN 100000
#define EE 1600000
#define HH 128
#define GG 2048
#define KK 5
#define LL 3
#define EPS 1e-5f

// ---------------- scratch (device globals; no allocation allowed) ----------------
__device__ int   g_indeg[NN];
__device__ int   g_rowptr[NN + 1];
__device__ int   g_cursor[NN];
__device__ float g_dinv[NN];
__device__ uint2 g_csr[EE];                 // (src, weight-bits)
__device__ float g_hW[(size_t)NN * HH];
__device__ float g_agg[(size_t)NN * HH];
__device__ float g_h[(size_t)NN * HH];
__device__ float g_stats[2 * HH];           // [sum, sumsq]
__device__ float g_scale[HH];
__device__ float g_shift[HH];
__device__ float g_pooled[GG * HH];
__device__ float g_cnt[GG];

// ---------------- setup kernels ----------------
__global__ void k_init() {
    int i = blockIdx.x * blockDim.x + threadIdx.x;   // grid covers 262144
    if (i < GG * HH) g_pooled[i] = 0.f;
    if (i < GG)      g_cnt[i] = 0.f;
    if (i < NN)      g_indeg[i] = 0;
}

__global__ void k_hist(const int* __restrict__ dst) {
    int e = blockIdx.x * blockDim.x + threadIdx.x;
    if (e < EE) atomicAdd(&g_indeg[dst[e]], 1);
}

__global__ void k_dinv() {
    int i = blockIdx.x * blockDim.x + threadIdx.x;
    if (i < NN) g_dinv[i] = rsqrtf(1.0f + (float)g_indeg[i]);
}

// single-block exclusive scan of g_indeg -> g_rowptr / g_cursor
__global__ void k_scan() {
    __shared__ int s[1024];
    const int CH = 98;  // 1024*98 >= 100000
    int t = threadIdx.x;
    int beg = t * CH, end = min(beg + CH, NN);
    int own = 0;
    for (int i = beg; i < end; i++) own += g_indeg[i];
    s[t] = own;
    __syncthreads();
    for (int off = 1; off < 1024; off <<= 1) {
        int v = (t >= off) ? s[t - off] : 0;
        __syncthreads();
        s[t] += v;
        __syncthreads();
    }
    int excl = s[t] - own;
    int run = excl;
    for (int i = beg; i < end; i++) {
        g_rowptr[i] = run;
        g_cursor[i] = run;
        run += g_indeg[i];
    }
    if (t == 1023) g_rowptr[NN] = excl;   // == EE (last chunk is empty)
}

__global__ void k_scatter(const int* __restrict__ src, const int* __restrict__ dst) {
    int e = blockIdx.x * blockDim.x + threadIdx.x;
    if (e >= EE) return;
    int s = src[e], d = dst[e];
    int pos = atomicAdd(&g_cursor[d], 1);
    float w = g_dinv[s] * g_dinv[d];
    g_csr[pos] = make_uint2((unsigned)s, __float_as_uint(w));
}

// ---------------- GEMM: hW = h @ W (128x128), half of cols per blockIdx.y ----------------
__global__ void __launch_bounds__(256) k_gemm(const float* __restrict__ h,
                                              const float* __restrict__ W) {
    __shared__ float sW[128 * 64];   // 32 KB: cols [y*64, y*64+64)
    __shared__ float sH[8 * 128];    // 4 KB: 8 rows of h
    int tid = threadIdx.x;
    int ybase = blockIdx.y * 16;     // in float4 units (64 floats)
    const float4* W4 = (const float4*)W;
    float4* sW4 = (float4*)sW;
    #pragma unroll
    for (int i = tid; i < 2048; i += 256) {
        int k = i >> 4, cc = i & 15;
        sW4[i] = W4[k * 32 + ybase + cc];
    }
    int row0 = blockIdx.x * 8;
    const float4* h4 = (const float4*)h;
    float4* sH4 = (float4*)sH;
    sH4[tid] = h4[(size_t)row0 * 32 + tid];   // N divisible by 8 -> no bounds
    if (blockIdx.x == 0 && blockIdx.y == 0) g_stats[tid] = 0.f;  // 256 entries
    __syncthreads();

    int warp = tid >> 5, lane = tid & 31;
    int row = row0 + warp;
    const float2* sW2 = (const float2*)sW;
    float2 acc = make_float2(0.f, 0.f);
    #pragma unroll
    for (int kk = 0; kk < 32; kk++) {
        float4 hb = sH4[warp * 32 + kk];          // uniform -> broadcast
        float2 w0 = sW2[(4 * kk + 0) * 32 + lane];
        float2 w1 = sW2[(4 * kk + 1) * 32 + lane];
        float2 w2 = sW2[(4 * kk + 2) * 32 + lane];
        float2 w3 = sW2[(4 * kk + 3) * 32 + lane];
        acc.x = fmaf(hb.x, w0.x, acc.x); acc.y = fmaf(hb.x, w0.y, acc.y);
        acc.x = fmaf(hb.y, w1.x, acc.x); acc.y = fmaf(hb.y, w1.y, acc.y);
        acc.x = fmaf(hb.z, w2.x, acc.x); acc.y = fmaf(hb.z, w2.y, acc.y);
        acc.x = fmaf(hb.w, w3.x, acc.x); acc.y = fmaf(hb.w, w3.y, acc.y);
    }
    float2* out = (float2*)(g_hW + (size_t)row * 128 + blockIdx.y * 64);
    out[lane] = acc;
}

// ---------------- aggregation (CSR gather) + self-loop + bias + BN stat accumulation ----
__global__ void __launch_bounds__(256) k_agg(const float* __restrict__ bl) {
    __shared__ float red[8 * 128];
    int tid = threadIdx.x;
    int warp = tid >> 5, lane = tid & 31;
    float s1x = 0.f, s1y = 0.f, s1z = 0.f, s1w = 0.f;
    float s2x = 0.f, s2y = 0.f, s2z = 0.f, s2w = 0.f;
    float4 bb = __ldg((const float4*)bl + lane);
    const float4* hW4 = (const float4*)g_hW;

    for (int node = blockIdx.x * 8 + warp; node < NN; node += gridDim.x * 8) {
        int start = g_rowptr[node];
        int end   = g_rowptr[node + 1];
        float dv = g_dinv[node];
        float4 hs = __ldg(hW4 + (size_t)node * 32 + lane);
        float sn = dv * dv;
        float4 acc;
        acc.x = fmaf(hs.x, sn, bb.x);
        acc.y = fmaf(hs.y, sn, bb.y);
        acc.z = fmaf(hs.z, sn, bb.z);
        acc.w = fmaf(hs.w, sn, bb.w);
        int e = start;
        for (; e + 4 <= end; e += 4) {
            uint2 c0 = __ldg(&g_csr[e + 0]);
            uint2 c1 = __ldg(&g_csr[e + 1]);
            uint2 c2 = __ldg(&g_csr[e + 2]);
            uint2 c3 = __ldg(&g_csr[e + 3]);
            float4 v0 = __ldg(hW4 + (size_t)c0.x * 32 + lane);
            float4 v1 = __ldg(hW4 + (size_t)c1.x * 32 + lane);
            float4 v2 = __ldg(hW4 + (size_t)c2.x * 32 + lane);
            float4 v3 = __ldg(hW4 + (size_t)c3.x * 32 + lane);
            float w0 = __uint_as_float(c0.y), w1 = __uint_as_float(c1.y);
            float w2 = __uint_as_float(c2.y), w3 = __uint_as_float(c3.y);
            acc.x = fmaf(w0, v0.x, acc.x); acc.y = fmaf(w0, v0.y, acc.y);
            acc.z = fmaf(w0, v0.z, acc.z); acc.w = fmaf(w0, v0.w, acc.w);
            acc.x = fmaf(w1, v1.x, acc.x); acc.y = fmaf(w1, v1.y, acc.y);
            acc.z = fmaf(w1, v1.z, acc.z); acc.w = fmaf(w1, v1.w, acc.w);
            acc.x = fmaf(w2, v2.x, acc.x); acc.y = fmaf(w2, v2.y, acc.y);
            acc.z = fmaf(w2, v2.z, acc.z); acc.w = fmaf(w2, v2.w, acc.w);
            acc.x = fmaf(w3, v3.x, acc.x); acc.y = fmaf(w3, v3.y, acc.y);
            acc.z = fmaf(w3, v3.z, acc.z); acc.w = fmaf(w3, v3.w, acc.w);
        }
        for (; e < end; e++) {
            uint2 c0 = __ldg(&g_csr[e]);
            float4 v0 = __ldg(hW4 + (size_t)c0.x * 32 + lane);
            float w0 = __uint_as_float(c0.y);
            acc.x = fmaf(w0, v0.x, acc.x); acc.y = fmaf(w0, v0.y, acc.y);
            acc.z = fmaf(w0, v0.z, acc.z); acc.w = fmaf(w0, v0.w, acc.w);
        }
        ((float4*)(g_agg + (size_t)node * 128))[lane] = acc;
        s1x += acc.x; s1y += acc.y; s1z += acc.z; s1w += acc.w;
        s2x = fmaf(acc.x, acc.x, s2x); s2y = fmaf(acc.y, acc.y, s2y);
        s2z = fmaf(acc.z, acc.z, s2z); s2w = fmaf(acc.w, acc.w, s2w);
    }
    // reduce block stats -> global
    int c = lane * 4;
    red[warp * 128 + c + 0] = s1x; red[warp * 128 + c + 1] = s1y;
    red[warp * 128 + c + 2] = s1z; red[warp * 128 + c + 3] = s1w;
    __syncthreads();
    if (tid < 128) {
        float t = 0.f;
        #pragma unroll
        for (int w = 0; w < 8; w++) t += red[w * 128 + tid];
        atomicAdd(&g_stats[tid], t);
    }
    __syncthreads();
    red[warp * 128 + c + 0] = s2x; red[warp * 128 + c + 1] = s2y;
    red[warp * 128 + c + 2] = s2z; red[warp * 128 + c + 3] = s2w;
    __syncthreads();
    if (tid < 128) {
        float t = 0.f;
        #pragma unroll
        for (int w = 0; w < 8; w++) t += red[w * 128 + tid];
        atomicAdd(&g_stats[128 + tid], t);
    }
}

__global__ void k_bnfinal(const float* __restrict__ gamma, const float* __restrict__ beta) {
    int c = threadIdx.x;  // 128
    float s1 = g_stats[c], s2 = g_stats[128 + c];
    float mu = s1 * (1.0f / NN);
    float var = s2 * (1.0f / NN) - mu * mu;
    float inv = rsqrtf(var + EPS);
    float sc = __ldg(&gamma[c]) * inv;
    g_scale[c] = sc;
    g_shift[c] = __ldg(&beta[c]) - mu * sc;
}

__global__ void k_norm() {
    int i = blockIdx.x * blockDim.x + threadIdx.x;   // N*32 elements (float4)
    const float4* a4 = (const float4*)g_agg;
    float4 a = a4[i];
    int c4 = i & 31;
    float4 sc = __ldg((const float4*)g_scale + c4);
    float4 sh = __ldg((const float4*)g_shift + c4);
    float4 o;
    o.x = fmaxf(fmaf(a.x, sc.x, sh.x), 0.f);
    o.y = fmaxf(fmaf(a.y, sc.y, sh.y), 0.f);
    o.z = fmaxf(fmaf(a.z, sc.z, sh.z), 0.f);
    o.w = fmaxf(fmaf(a.w, sc.w, sh.w), 0.f);
    ((float4*)g_h)[i] = o;
}

// ---------------- pooling (batch is sorted -> run-length flush) ----------------
__global__ void k_pool(const int* __restrict__ batch) {
    int gw = (blockIdx.x * blockDim.x + threadIdx.x) >> 5;
    int lane = threadIdx.x & 31;
    int base = gw * 8;
    if (base >= NN) return;
    const float4* h4 = (const float4*)g_h;
    float4 acc = make_float4(0.f, 0.f, 0.f, 0.f);
    int cur = -1;
    float cnt = 0.f;
    for (int i = 0; i < 8; i++) {
        int n = base + i;
        if (n >= NN) break;
        int gb = __ldg(&batch[n]);
        if (gb != cur) {
            if (cur >= 0) {
                float* p = g_pooled + cur * 128 + lane * 4;
                atomicAdd(p + 0, acc.x); atomicAdd(p + 1, acc.y);
                atomicAdd(p + 2, acc.z); atomicAdd(p + 3, acc.w);
                if (lane == 0) atomicAdd(&g_cnt[cur], cnt);
            }
            cur = gb; acc = make_float4(0.f, 0.f, 0.f, 0.f); cnt = 0.f;
        }
        float4 v = __ldg(h4 + (size_t)n * 32 + lane);
        acc.x += v.x; acc.y += v.y; acc.z += v.z; acc.w += v.w;
        cnt += 1.f;
    }
    if (cur >= 0) {
        float* p = g_pooled + cur * 128 + lane * 4;
        atomicAdd(p + 0, acc.x); atomicAdd(p + 1, acc.y);
        atomicAdd(p + 2, acc.z); atomicAdd(p + 3, acc.w);
        if (lane == 0) atomicAdd(&g_cnt[cur], cnt);
    }
}

// ---------------- heads: 8 graphs per block ----------------
__global__ void __launch_bounds__(320) k_heads(const float* __restrict__ HW1,
                                               const float* __restrict__ Hb1,
                                               const float* __restrict__ HW2,
                                               const float* __restrict__ Hb2,
                                               float* __restrict__ out) {
    __shared__ float sp[8 * 128];
    __shared__ float sz[8 * 320];
    int tid = threadIdx.x;
    int g0 = blockIdx.x * 8;
    for (int i = tid; i < 1024; i += 320) {
        int j = i >> 7, c = i & 127;
        float cnt = g_cnt[g0 + j];
        sp[i] = g_pooled[(g0 + j) * 128 + c] / fmaxf(cnt, 1.f);
    }
    __syncthreads();
    int k = tid / 64, m = tid % 64;   // tid < 320 always
    float acc[8];
    #pragma unroll
    for (int j = 0; j < 8; j++) acc[j] = 0.f;
    const float* w = HW1 + k * (128 * 64) + m;
    #pragma unroll 4
    for (int h = 0; h < 128; h++) {
        float wv = __ldg(w + h * 64);
        #pragma unroll
        for (int j = 0; j < 8; j++) acc[j] = fmaf(sp[j * 128 + h], wv, acc[j]);
    }
    float b1 = __ldg(&Hb1[k * 64 + m]);
    #pragma unroll
    for (int j = 0; j < 8; j++) sz[j * 320 + k * 64 + m] = fmaxf(acc[j] + b1, 0.f);
    __syncthreads();
    if (tid < 40) {
        int j = tid / 5, kk = tid % 5;
        float s = __ldg(&Hb2[kk]);
        const float* w2 = HW2 + kk * 64;
        const float* zz = &sz[j * 320 + kk * 64];
        #pragma unroll
        for (int mm = 0; mm < 64; mm++) s = fmaf(zz[mm], __ldg(&w2[mm]), s);
        out[kk * GG + g0 + j] = s;
    }
}

// ---------------- launch ----------------
extern "C" void kernel_launch(void* const* d_in, const int* in_sizes, int n_in,
                              void* d_out, int out_size) {
    const float* x     = (const float*)d_in[0];
    const int*   ei    = (const int*)d_in[1];
    const int*   batch = (const int*)d_in[3];
    const float* W0    = (const float*)d_in[4];
    const float* Wrest = (const float*)d_in[5];
    const float* b     = (const float*)d_in[6];
    const float* gamma = (const float*)d_in[7];
    const float* beta  = (const float*)d_in[8];
    const float* HW1   = (const float*)d_in[9];
    const float* Hb1   = (const float*)d_in[10];
    const float* HW2   = (const float*)d_in[11];
    const float* Hb2   = (const float*)d_in[12];
    float* out = (float*)d_out;

    const int* src = ei;
    const int* dst = ei + EE;

    k_init<<<1024, 256>>>();
    k_hist<<<(EE + 255) / 256, 256>>>(dst);
    k_dinv<<<(NN + 255) / 256, 256>>>();
    k_scan<<<1, 1024>>>();
    k_scatter<<<(EE + 255) / 256, 256>>>(src, dst);

    float* gh = nullptr;
    cudaGetSymbolAddress((void**)&gh, g_h);

    for (int l = 0; l < LL; l++) {
        const float* h = (l == 0) ? x : gh;
        const float* W = (l == 0) ? W0 : (Wrest + (size_t)(l - 1) * HH * HH);
        dim3 ggrid(NN / 8, 2);
        k_gemm<<<ggrid, 256>>>(h, W);
        k_agg<<<1184, 256>>>(b + l * HH);
        k_bnfinal<<<1, 128>>>(gamma + l * HH, beta + l * HH);
        k_norm<<<NN * 32 / 256, 256>>>();
    }

    k_pool<<<(NN / 8 + 7) / 8, 256>>>(batch);
    k_heads<<<GG / 8, 320>>>(HW1, Hb1, HW2, Hb2, out);
}

// round 2
// speedup vs baseline: 2.3186x; 2.3186x over previous
#include <cuda_runtime.h>
#include <cuda_bf16.h>
#include <stdint.h>

#define NN 100000
#define EE 1600000
#define HH 128
#define GG 2048
#define KK 5
#define LL 3
#define EPS 1e-5f

// ---------------- scratch (device globals; no allocation allowed) ----------------
__device__ int   g_indeg[NN];
__device__ int   g_rowptr[NN + 1];
__device__ int   g_cursor[NN];
__device__ float g_dinv[NN];
__device__ uint2 g_csr[EE];                 // (src, weight-bits)
__device__ float g_hW[(size_t)NN * HH];
__device__ float g_agg[(size_t)NN * HH];
__device__ float g_stats[2 * HH];           // [sum, sumsq]
__device__ float g_scale[HH];
__device__ float g_shift[HH];
__device__ float g_pooled[GG * HH];
__device__ float g_cnt[GG];
__device__ int   g_bsum[512];
__device__ int   g_boff[512];

// ---------------- setup kernels ----------------
__global__ void k_init() {
    int i = blockIdx.x * blockDim.x + threadIdx.x;   // grid covers 262144
    if (i < GG * HH) g_pooled[i] = 0.f;
    if (i < GG)      g_cnt[i] = 0.f;
    if (i < NN)      g_indeg[i] = 0;
    if (i < 2 * HH)  g_stats[i] = 0.f;
}

__global__ void k_hist(const int* __restrict__ dst) {
    int e = blockIdx.x * blockDim.x + threadIdx.x;
    if (e < EE) atomicAdd(&g_indeg[dst[e]], 1);
}

// phase 1: per-block degree sums (+ dinv, fused)
__global__ void k_scan1() {
    int i = blockIdx.x * 256 + threadIdx.x;
    int v = (i < NN) ? g_indeg[i] : 0;
    if (i < NN) g_dinv[i] = rsqrtf(1.0f + (float)v);
    #pragma unroll
    for (int o = 16; o; o >>= 1) v += __shfl_down_sync(0xffffffffu, v, o);
    __shared__ int ws[8];
    if ((threadIdx.x & 31) == 0) ws[threadIdx.x >> 5] = v;
    __syncthreads();
    if (threadIdx.x < 8) {
        int t = ws[threadIdx.x];
        #pragma unroll
        for (int o = 4; o; o >>= 1) t += __shfl_down_sync(0xffu, t, o);
        if (threadIdx.x == 0) g_bsum[blockIdx.x] = t;
    }
}

// phase 2: exclusive scan of 391 block sums (1 block, 512 thr)
__global__ void k_scan2() {
    __shared__ int s[512];
    int t = threadIdx.x;
    int v = (t < 391) ? g_bsum[t] : 0;
    s[t] = v;
    __syncthreads();
    for (int o = 1; o < 512; o <<= 1) {
        int u = (t >= o) ? s[t - o] : 0;
        __syncthreads();
        s[t] += u;
        __syncthreads();
    }
    g_boff[t] = s[t] - v;
}

// phase 3: per-element exclusive scan -> rowptr/cursor
__global__ void k_scan3() {
    int i = blockIdx.x * 256 + threadIdx.x;
    int lane = threadIdx.x & 31, warp = threadIdx.x >> 5;
    int v = (i < NN) ? g_indeg[i] : 0;
    int inc = v;
    #pragma unroll
    for (int o = 1; o < 32; o <<= 1) {
        int u = __shfl_up_sync(0xffffffffu, inc, o);
        if (lane >= o) inc += u;
    }
    __shared__ int ws[8], wo[8];
    if (lane == 31) ws[warp] = inc;
    __syncthreads();
    if (threadIdx.x == 0) {
        int run = 0;
        #pragma unroll
        for (int w = 0; w < 8; w++) { wo[w] = run; run += ws[w]; }
    }
    __syncthreads();
    int excl = inc - v + wo[warp] + g_boff[blockIdx.x];
    if (i < NN) { g_rowptr[i] = excl; g_cursor[i] = excl; }
    if (i == NN - 1) g_rowptr[NN] = excl + v;
}

__global__ void k_scatter(const int* __restrict__ src, const int* __restrict__ dst) {
    int e = blockIdx.x * blockDim.x + threadIdx.x;
    if (e >= EE) return;
    int s = src[e], d = dst[e];
    int pos = atomicAdd(&g_cursor[d], 1);
    float w = g_dinv[s] * g_dinv[d];
    g_csr[pos] = make_uint2((unsigned)s, __float_as_uint(w));
}

// ---------------- GEMM: hW = h @ W, 64 rows/block, 8x4 register tile ---------
// fuse=1: input is g_agg, apply scale/shift + relu while staging sH.
__global__ void __launch_bounds__(256) k_gemm(const float* __restrict__ h,
                                              const float* __restrict__ W,
                                              int fuse) {
    extern __shared__ float smem[];
    float* sW = smem;            // 128*128 floats = 64 KB
    float* sH = smem + 16384;    // 64*128 floats = 32 KB
    int tid = threadIdx.x;
    float4* sW4 = (float4*)sW;
    const float4* W4 = (const float4*)W;
    #pragma unroll
    for (int i = tid; i < 4096; i += 256) sW4[i] = __ldg(W4 + i);

    int row0 = blockIdx.x * 64;
    const float4* h4 = (const float4*)h;
    float4* sH4 = (float4*)sH;
    if (fuse) {
        #pragma unroll
        for (int i = tid; i < 2048; i += 256) {
            int r = i >> 5, c = i & 31;
            int row = row0 + r;
            float4 v = (row < NN) ? __ldg(h4 + (size_t)row * 32 + c)
                                  : make_float4(0.f, 0.f, 0.f, 0.f);
            float4 sc = __ldg((const float4*)g_scale + c);
            float4 sh = __ldg((const float4*)g_shift + c);
            v.x = fmaxf(fmaf(v.x, sc.x, sh.x), 0.f);
            v.y = fmaxf(fmaf(v.y, sc.y, sh.y), 0.f);
            v.z = fmaxf(fmaf(v.z, sc.z, sh.z), 0.f);
            v.w = fmaxf(fmaf(v.w, sc.w, sh.w), 0.f);
            sH4[i] = v;
        }
    } else {
        #pragma unroll
        for (int i = tid; i < 2048; i += 256) {
            int r = i >> 5, c = i & 31;
            int row = row0 + r;
            sH4[i] = (row < NN) ? __ldg(h4 + (size_t)row * 32 + c)
                                : make_float4(0.f, 0.f, 0.f, 0.f);
        }
    }
    __syncthreads();

    int warp = tid >> 5, lane = tid & 31;
    float4 acc[8];
    #pragma unroll
    for (int r = 0; r < 8; r++) acc[r] = make_float4(0.f, 0.f, 0.f, 0.f);
    const float4* sWl = sW4 + lane;
    const float* sHrow = sH + (warp * 8) * 128;

    #pragma unroll 4
    for (int k = 0; k < 128; k++) {
        float4 w = sWl[k * 32];
        #pragma unroll
        for (int r = 0; r < 8; r++) {
            float hv = sHrow[r * 128 + k];
            acc[r].x = fmaf(hv, w.x, acc[r].x);
            acc[r].y = fmaf(hv, w.y, acc[r].y);
            acc[r].z = fmaf(hv, w.z, acc[r].z);
            acc[r].w = fmaf(hv, w.w, acc[r].w);
        }
    }
    int rbase = row0 + warp * 8;
    #pragma unroll
    for (int r = 0; r < 8; r++) {
        int row = rbase + r;
        if (row < NN) ((float4*)(g_hW + (size_t)row * 128))[lane] = acc[r];
    }
}

// ---------------- aggregation (CSR gather) + self-loop + bias + BN stats ------
__global__ void __launch_bounds__(256) k_agg(const float* __restrict__ bl) {
    __shared__ float red[8 * 128];
    int tid = threadIdx.x;
    int warp = tid >> 5, lane = tid & 31;
    float s1x = 0.f, s1y = 0.f, s1z = 0.f, s1w = 0.f;
    float s2x = 0.f, s2y = 0.f, s2z = 0.f, s2w = 0.f;
    float4 bb = __ldg((const float4*)bl + lane);
    const float4* hW4 = (const float4*)g_hW;

    for (int node = blockIdx.x * 8 + warp; node < NN; node += gridDim.x * 8) {
        int start = g_rowptr[node];
        int end   = g_rowptr[node + 1];
        float dv = g_dinv[node];
        float4 hs = __ldg(hW4 + (size_t)node * 32 + lane);
        float sn = dv * dv;
        float4 acc;
        acc.x = fmaf(hs.x, sn, bb.x);
        acc.y = fmaf(hs.y, sn, bb.y);
        acc.z = fmaf(hs.z, sn, bb.z);
        acc.w = fmaf(hs.w, sn, bb.w);
        int e = start;
        for (; e + 4 <= end; e += 4) {
            uint2 c0 = __ldg(&g_csr[e + 0]);
            uint2 c1 = __ldg(&g_csr[e + 1]);
            uint2 c2 = __ldg(&g_csr[e + 2]);
            uint2 c3 = __ldg(&g_csr[e + 3]);
            float4 v0 = __ldg(hW4 + (size_t)c0.x * 32 + lane);
            float4 v1 = __ldg(hW4 + (size_t)c1.x * 32 + lane);
            float4 v2 = __ldg(hW4 + (size_t)c2.x * 32 + lane);
            float4 v3 = __ldg(hW4 + (size_t)c3.x * 32 + lane);
            float w0 = __uint_as_float(c0.y), w1 = __uint_as_float(c1.y);
            float w2 = __uint_as_float(c2.y), w3 = __uint_as_float(c3.y);
            acc.x = fmaf(w0, v0.x, acc.x); acc.y = fmaf(w0, v0.y, acc.y);
            acc.z = fmaf(w0, v0.z, acc.z); acc.w = fmaf(w0, v0.w, acc.w);
            acc.x = fmaf(w1, v1.x, acc.x); acc.y = fmaf(w1, v1.y, acc.y);
            acc.z = fmaf(w1, v1.z, acc.z); acc.w = fmaf(w1, v1.w, acc.w);
            acc.x = fmaf(w2, v2.x, acc.x); acc.y = fmaf(w2, v2.y, acc.y);
            acc.z = fmaf(w2, v2.z, acc.z); acc.w = fmaf(w2, v2.w, acc.w);
            acc.x = fmaf(w3, v3.x, acc.x); acc.y = fmaf(w3, v3.y, acc.y);
            acc.z = fmaf(w3, v3.z, acc.z); acc.w = fmaf(w3, v3.w, acc.w);
        }
        for (; e < end; e++) {
            uint2 c0 = __ldg(&g_csr[e]);
            float4 v0 = __ldg(hW4 + (size_t)c0.x * 32 + lane);
            float w0 = __uint_as_float(c0.y);
            acc.x = fmaf(w0, v0.x, acc.x); acc.y = fmaf(w0, v0.y, acc.y);
            acc.z = fmaf(w0, v0.z, acc.z); acc.w = fmaf(w0, v0.w, acc.w);
        }
        ((float4*)(g_agg + (size_t)node * 128))[lane] = acc;
        s1x += acc.x; s1y += acc.y; s1z += acc.z; s1w += acc.w;
        s2x = fmaf(acc.x, acc.x, s2x); s2y = fmaf(acc.y, acc.y, s2y);
        s2z = fmaf(acc.z, acc.z, s2z); s2w = fmaf(acc.w, acc.w, s2w);
    }
    int c = lane * 4;
    red[warp * 128 + c + 0] = s1x; red[warp * 128 + c + 1] = s1y;
    red[warp * 128 + c + 2] = s1z; red[warp * 128 + c + 3] = s1w;
    __syncthreads();
    if (tid < 128) {
        float t = 0.f;
        #pragma unroll
        for (int w = 0; w < 8; w++) t += red[w * 128 + tid];
        atomicAdd(&g_stats[tid], t);
    }
    __syncthreads();
    red[warp * 128 + c + 0] = s2x; red[warp * 128 + c + 1] = s2y;
    red[warp * 128 + c + 2] = s2z; red[warp * 128 + c + 3] = s2w;
    __syncthreads();
    if (tid < 128) {
        float t = 0.f;
        #pragma unroll
        for (int w = 0; w < 8; w++) t += red[w * 128 + tid];
        atomicAdd(&g_stats[128 + tid], t);
    }
}

// compute scale/shift and reset stats for next layer
__global__ void k_bnfinal(const float* __restrict__ gamma, const float* __restrict__ beta) {
    int c = threadIdx.x;  // 128
    float s1 = g_stats[c], s2 = g_stats[128 + c];
    float mu = s1 * (1.0f / NN);
    float var = s2 * (1.0f / NN) - mu * mu;
    float inv = rsqrtf(var + EPS);
    float sc = __ldg(&gamma[c]) * inv;
    g_scale[c] = sc;
    g_shift[c] = __ldg(&beta[c]) - mu * sc;
    g_stats[c] = 0.f;
    g_stats[128 + c] = 0.f;
}

// ---------------- pooling with fused normalize+relu (batch sorted) ------------
__global__ void k_pool(const int* __restrict__ batch) {
    int gw = (blockIdx.x * blockDim.x + threadIdx.x) >> 5;
    int lane = threadIdx.x & 31;
    int base = gw * 8;
    if (base >= NN) return;
    const float4* a4 = (const float4*)g_agg;
    float4 sc = __ldg((const float4*)g_scale + lane);
    float4 sh = __ldg((const float4*)g_shift + lane);
    float4 acc = make_float4(0.f, 0.f, 0.f, 0.f);
    int cur = -1;
    float cnt = 0.f;
    for (int i = 0; i < 8; i++) {
        int n = base + i;
        if (n >= NN) break;
        int gb = __ldg(&batch[n]);
        if (gb != cur) {
            if (cur >= 0) {
                float* p = g_pooled + cur * 128 + lane * 4;
                atomicAdd(p + 0, acc.x); atomicAdd(p + 1, acc.y);
                atomicAdd(p + 2, acc.z); atomicAdd(p + 3, acc.w);
                if (lane == 0) atomicAdd(&g_cnt[cur], cnt);
            }
            cur = gb; acc = make_float4(0.f, 0.f, 0.f, 0.f); cnt = 0.f;
        }
        float4 v = __ldg(a4 + (size_t)n * 32 + lane);
        acc.x += fmaxf(fmaf(v.x, sc.x, sh.x), 0.f);
        acc.y += fmaxf(fmaf(v.y, sc.y, sh.y), 0.f);
        acc.z += fmaxf(fmaf(v.z, sc.z, sh.z), 0.f);
        acc.w += fmaxf(fmaf(v.w, sc.w, sh.w), 0.f);
        cnt += 1.f;
    }
    if (cur >= 0) {
        float* p = g_pooled + cur * 128 + lane * 4;
        atomicAdd(p + 0, acc.x); atomicAdd(p + 1, acc.y);
        atomicAdd(p + 2, acc.z); atomicAdd(p + 3, acc.w);
        if (lane == 0) atomicAdd(&g_cnt[cur], cnt);
    }
}

// ---------------- heads: 8 graphs per block ----------------
__global__ void __launch_bounds__(320) k_heads(const float* __restrict__ HW1,
                                               const float* __restrict__ Hb1,
                                               const float* __restrict__ HW2,
                                               const float* __restrict__ Hb2,
                                               float* __restrict__ out) {
    __shared__ float sp[8 * 128];
    __shared__ float sz[8 * 320];
    int tid = threadIdx.x;
    int g0 = blockIdx.x * 8;
    for (int i = tid; i < 1024; i += 320) {
        int j = i >> 7, c = i & 127;
        float cnt = g_cnt[g0 + j];
        sp[i] = g_pooled[(g0 + j) * 128 + c] / fmaxf(cnt, 1.f);
    }
    __syncthreads();
    int k = tid / 64, m = tid % 64;
    float acc[8];
    #pragma unroll
    for (int j = 0; j < 8; j++) acc[j] = 0.f;
    const float* w = HW1 + k * (128 * 64) + m;
    #pragma unroll 4
    for (int h = 0; h < 128; h++) {
        float wv = __ldg(w + h * 64);
        #pragma unroll
        for (int j = 0; j < 8; j++) acc[j] = fmaf(sp[j * 128 + h], wv, acc[j]);
    }
    float b1 = __ldg(&Hb1[k * 64 + m]);
    #pragma unroll
    for (int j = 0; j < 8; j++) sz[j * 320 + k * 64 + m] = fmaxf(acc[j] + b1, 0.f);
    __syncthreads();
    if (tid < 40) {
        int j = tid / 5, kk = tid % 5;
        float s = __ldg(&Hb2[kk]);
        const float* w2 = HW2 + kk * 64;
        const float* zz = &sz[j * 320 + kk * 64];
        #pragma unroll
        for (int mm = 0; mm < 64; mm++) s = fmaf(zz[mm], __ldg(&w2[mm]), s);
        out[kk * GG + g0 + j] = s;
    }
}

// ---------------- launch ----------------
extern "C" void kernel_launch(void* const* d_in, const int* in_sizes, int n_in,
                              void* d_out, int out_size) {
    const float* x     = (const float*)d_in[0];
    const int*   ei    = (const int*)d_in[1];
    const int*   batch = (const int*)d_in[3];
    const float* W0    = (const float*)d_in[4];
    const float* Wrest = (const float*)d_in[5];
    const float* b     = (const float*)d_in[6];
    const float* gamma = (const float*)d_in[7];
    const float* beta  = (const float*)d_in[8];
    const float* HW1   = (const float*)d_in[9];
    const float* Hb1   = (const float*)d_in[10];
    const float* HW2   = (const float*)d_in[11];
    const float* Hb2   = (const float*)d_in[12];
    float* out = (float*)d_out;

    const int* src = ei;
    const int* dst = ei + EE;

    static int s_attr_done = 0;
    if (!s_attr_done) {
        cudaFuncSetAttribute(k_gemm, cudaFuncAttributeMaxDynamicSharedMemorySize, 98304);
        s_attr_done = 1;
    }

    k_init<<<1024, 256>>>();
    k_hist<<<(EE + 255) / 256, 256>>>(dst);
    k_scan1<<<391, 256>>>();
    k_scan2<<<1, 512>>>();
    k_scan3<<<391, 256>>>();
    k_scatter<<<(EE + 255) / 256, 256>>>(src, dst);

    float* gagg = nullptr;
    cudaGetSymbolAddress((void**)&gagg, g_agg);

    for (int l = 0; l < LL; l++) {
        const float* h = (l == 0) ? x : gagg;
        const float* W = (l == 0) ? W0 : (Wrest + (size_t)(l - 1) * HH * HH);
        k_gemm<<<(NN + 63) / 64, 256, 98304>>>(h, W, l > 0 ? 1 : 0);
        k_agg<<<1184, 256>>>(b + l * HH);
        k_bnfinal<<<1, 128>>>(gamma + l * HH, beta + l * HH);
    }

    k_pool<<<(NN / 8 + 7) / 8, 256>>>(batch);
    k_heads<<<GG / 8, 320>>>(HW1, Hb1, HW2, Hb2, out);
}